// round 12
// baseline (speedup 1.0000x reference)
#include <cuda_runtime.h>

// Fixed problem shapes: B=4, L=80000, N=512, F=257, STRIDE=256 -> T=311
#define NB  4
#define NL  80000
#define NN  512
#define NF  257
#define NT  311
#define BFT (NB * NF * NT)   // 319708

#define TWO_PI 6.2831853071795864769f
#define PI_F   3.1415926535897932385f

// ---- Precomputed tables (allocation-free __device__ globals) ----
__device__ float  g_tap[NT][NN];       // window taps per (frame, n)
__device__ float  g_frac[NT];
__device__ int    g_i0[NT];
__device__ float4 g_twsh[5][32];       // shfl stages h=16..1: (cos, sin, sign, 0)
__device__ float2 g_tw64[2][32];       // H=64 stage, k=0/1
__device__ float2 g_tw32[32];          // H=32 stage
__device__ float2 g_w4[4][4][32];      // radix-4 exchange: [m][k][l]

// ---------------------------------------------------------------------------
// Prep: per-frame window taps + frac/i0, plus (block 0) all lane twiddles.
// Accurate trig (cheap here, runs once per launch).
// ---------------------------------------------------------------------------
__global__ void prep_kernel(const float* __restrict__ wlp,
                            const float* __restrict__ stp) {
    const int t   = blockIdx.x;
    const int tid = threadIdx.x;

    const float wl = fminf(fmaxf(wlp[0], 25.6f), 512.0f);   // WIN_MIN..WIN_MAX
    const float st = fminf(fmaxf(stp[0], 0.0f), 512.0f);    // STRIDE_MIN..MAX
    const float frame = st * (float)t;                       // == cumsum (broadcast stride)
    const float flo   = floorf(frame);
    const float frac  = frame - flo;
    if (tid == 0) { g_i0[t] = (int)flo; g_frac[t] = frac; }

    const float hi   = ceilf ((511.0f + wl) * 0.5f);
    const float lo   = floorf((511.0f - wl) * 0.5f);
    const float woff = (wl - 511.0f) * 0.5f;
#pragma unroll
    for (int h = 0; h < 2; ++h) {
        const int n = tid + h * 256;
        const float base = (float)n - frac;
        float tap = 0.0f;
        if (!(base >= hi || base <= lo))
            tap = (0.5f - 0.5f * cosf(TWO_PI * (base + woff) / wl)) * 0.00390625f;
        g_tap[t][n] = tap;
    }

    if (t == 0 && tid < 32) {
        const int l = tid;
        // shfl stages: h = 16 >> s
#pragma unroll
        for (int s = 0; s < 5; ++s) {
            const int h = 16 >> s;
            const int step = 16 / h;
            float sn, c;
            sincosf(-TWO_PI * (float)(step * (l & (h - 1))) * (1.0f / 32.0f), &sn, &c);
            const bool bot = (l & h) != 0;
            g_twsh[s][l] = bot ? make_float4(c, sn, -1.0f, 0.0f)
                               : make_float4(1.0f, 0.0f, 1.0f, 0.0f);
        }
        // local stages
        {
            float sn, c;
            sincosf(-TWO_PI * (float)l * (1.0f / 128.0f), &sn, &c);
            g_tw64[0][l] = make_float2(c, sn);
            sincosf(-TWO_PI * (float)(32 + l) * (1.0f / 128.0f), &sn, &c);
            g_tw64[1][l] = make_float2(c, sn);
            sincosf(-TWO_PI * (float)l * (1.0f / 64.0f), &sn, &c);
            g_tw32[l] = make_float2(c, sn);
        }
        // radix-4 exchange: wA = exp(iA), A = -(2*pi*l/512 + pi*k/8)
        // rows: m=0 -> 1, m=1 -> wA^2, m=2 -> wA, m=3 -> wA^3
#pragma unroll
        for (int k = 0; k < 4; ++k) {
            const float A = -(TWO_PI * (float)l * (1.0f / 512.0f)
                              + PI_F * (float)k * 0.125f);
            float s1, c1, s2, c2, s3, c3;
            sincosf(A, &s1, &c1);
            sincosf(2.0f * A, &s2, &c2);
            sincosf(3.0f * A, &s3, &c3);
            g_w4[0][k][l] = make_float2(1.0f, 0.0f);
            g_w4[1][k][l] = make_float2(c2, s2);
            g_w4[2][k][l] = make_float2(c1, s1);
            g_w4[3][k][l] = make_float2(c3, s3);
        }
    }
}

// ---------------------------------------------------------------------------
// Main: block = 128 threads (4 warps) per (frame t, batch b); grid (NT, NB).
// Structure identical to verified rounds 10-11, with all twiddles/taps loaded
// from tables and select-free shfl butterflies.
// Output layout: floats [0,BFT) = spec; [BFT,2*BFT) = real(stft).
// ---------------------------------------------------------------------------
__global__ void __launch_bounds__(128, 12)
adstft_kernel(const float* __restrict__ x, float* __restrict__ out) {
    __shared__ float2 sz[16][32];   // [kk][lane], 4 KB

    const int t = blockIdx.x;
    const int b = blockIdx.y;
    const int m = threadIdx.x >> 5;
    const int l = threadIdx.x & 31;

    const int   i0   = g_i0[t];
    const float frac = g_frac[t];

    // ---- Load + window (table) ----
    {
        const float* xb = x + b * NL;
#pragma unroll
        for (int k = 0; k < 4; ++k) {
            const int n   = 32 * (4 * m + k) + l;
            const int idx = i0 + n;
            const float v = (idx >= 0 && idx < NL) ? xb[idx] : 0.0f;
            sz[4 * m + k][l] = make_float2(v * g_tap[t][n], 0.0f);
        }
    }
    __syncthreads();

    // ---- Fused radix-4 cross-warp stages (H=256 then H=128) ----
    float zr[4], zi[4];
#pragma unroll
    for (int k = 0; k < 4; ++k) {
        const float2 W  = g_w4[m][k][l];
        const float2 c0 = sz[k     ][l];
        const float2 c1 = sz[k +  4][l];
        const float2 c2 = sz[k +  8][l];
        const float2 c3 = sz[k + 12][l];
        const float s0r = c0.x + c2.x, s0i = c0.y + c2.y;
        const float s1r = c1.x + c3.x, s1i = c1.y + c3.y;
        const float d0r = c0.x - c2.x, d0i = c0.y - c2.y;
        const float d1r = c1.x - c3.x, d1i = c1.y - c3.y;

        float er, ei;
        if (m == 0)      { er = s0r + s1r; ei = s0i + s1i; }   // B0 = s0+s1
        else if (m == 1) { er = s0r - s1r; ei = s0i - s1i; }   // *(wA^2)
        else if (m == 2) { er = d0r + d1i; ei = d0i - d1r; }   // (d0-i*d1)*wA
        else             { er = d0r - d1i; ei = d0i + d1r; }   // (d0+i*d1)*wA^3
        zr[k] = er * W.x - ei * W.y;
        zi[k] = er * W.y + ei * W.x;
    }

    // ---- Register-local stages H=64 (dist 2), H=32 (dist 1) ----
    {
#pragma unroll
        for (int k = 0; k < 2; ++k) {
            const float2 T = (k == 0) ? g_tw64[0][l] : g_tw64[1][l];
            const float dr = zr[k] - zr[k + 2];
            const float di = zi[k] - zi[k + 2];
            zr[k] += zr[k + 2];
            zi[k] += zi[k + 2];
            zr[k + 2] = fmaf(dr, T.x, -di * T.y);
            zi[k + 2] = fmaf(dr, T.y,  di * T.x);
        }
        const float2 T = g_tw32[l];
#pragma unroll
        for (int k = 0; k < 4; k += 2) {
            const float dr = zr[k] - zr[k + 1];
            const float di = zi[k] - zi[k + 1];
            zr[k] += zr[k + 1];
            zi[k] += zi[k + 1];
            zr[k + 1] = fmaf(dr, T.x, -di * T.y);
            zi[k + 1] = fmaf(dr, T.y,  di * T.x);
        }
    }

    // ---- Shfl stages H=16..1: select-free butterflies ----
#pragma unroll
    for (int s = 0; s < 5; ++s) {
        const int h = 16 >> s;
        const float4 TW = g_twsh[s][l];   // (cos, sin, sign)
#pragma unroll
        for (int k = 0; k < 4; ++k) {
            const float pr = __shfl_xor_sync(0xffffffffu, zr[k], h);
            const float pi = __shfl_xor_sync(0xffffffffu, zi[k], h);
            const float er = fmaf(TW.z, zr[k], pr);   // top: p+z, bottom: p-z
            const float ei = fmaf(TW.z, zi[k], pi);
            zr[k] = er * TW.x - ei * TW.y;            // top tw = (1,0)
            zi[k] = er * TW.y + ei * TW.x;
        }
    }

    // ---- Rebalanced emit: every lane outputs 2 frequencies ----
    const int q5 = ((l & 1) << 4) | ((l & 2) << 2) | (l & 4)
                 | ((l & 8) >> 2) | ((l & 16) >> 4);          // bitrev5(l)
    const int brm = ((m & 1) << 1) | (m >> 1);                // bitrev2(m)

    const float pr1 = __shfl_xor_sync(0xffffffffu, zr[1], 1);
    const float pi1 = __shfl_xor_sync(0xffffffffu, zi[1], 1);
    const float pr3 = __shfl_xor_sync(0xffffffffu, zr[3], 1);
    const float pi3 = __shfl_xor_sync(0xffffffffu, zi[3], 1);

    int f0, f1;
    float e0r, e0i, e1r, e1i;
    if ((l & 1) == 0) {            // own k=0 and k=2
        const int fbase = (q5 << 4) | brm;
        f0 = fbase;      e0r = zr[0]; e0i = zi[0];
        f1 = fbase | 4;  e1r = zr[2]; e1i = zi[2];
    } else {                       // partner fbase: bitrev5(l-1) = q5 - 16
        const int fbase = ((q5 - 16) << 4) | brm;
        f0 = fbase | 8;  e0r = pr1; e0i = pi1;
        f1 = fbase | 12; e1r = pr3; e1i = pi3;
    }

    {
        float sp, cp;
        __sincosf(TWO_PI * frac * (float)f0 * (1.0f / 512.0f), &sp, &cp);
        const float re = fmaf(e0r, cp, -e0i * sp);
        const float im = fmaf(e0r, sp,  e0i * cp);
        const int o = (b * NF + f0) * NT + t;
        out[o]       = sqrtf(fmaf(re, re, im * im)) + 1.1920929e-7f;
        out[BFT + o] = re;
    }
    {
        float sp, cp;
        __sincosf(TWO_PI * frac * (float)f1 * (1.0f / 512.0f), &sp, &cp);
        const float re = fmaf(e1r, cp, -e1i * sp);
        const float im = fmaf(e1r, sp,  e1i * cp);
        const int o = (b * NF + f1) * NT + t;
        out[o]       = sqrtf(fmaf(re, re, im * im)) + 1.1920929e-7f;
        out[BFT + o] = re;
    }

    if (l == 1 && m == 0) {        // f = 256 from own (q5=16, kk=0) slot
        float sp, cp;
        __sincosf(TWO_PI * frac * 0.5f, &sp, &cp);
        const float re = fmaf(zr[0], cp, -zi[0] * sp);
        const float im = fmaf(zr[0], sp,  zi[0] * cp);
        const int o = (b * NF + 256) * NT + t;
        out[o]       = sqrtf(fmaf(re, re, im * im)) + 1.1920929e-7f;
        out[BFT + o] = re;
    }
}

// ---------------------------------------------------------------------------
extern "C" void kernel_launch(void* const* d_in, const int* in_sizes, int n_in,
                              void* d_out, int out_size) {
    // x is the unique large input; win_length is the middle input under both
    // insertion and alphabetical order; strides is the remaining small one.
    int ix = 0;
    for (int i = 1; i < n_in; ++i)
        if (in_sizes[i] > in_sizes[ix]) ix = i;
    const float* x  = (const float*)d_in[ix];
    const float* wl = (const float*)d_in[1];
    const float* st = (const float*)d_in[(ix == 0) ? 2 : 0];
    float* out = (float*)d_out;

    prep_kernel<<<NT, 256>>>(wl, st);

    dim3 grid(NT, NB);
    adstft_kernel<<<grid, 128>>>(x, out);
}

// round 13
// speedup vs baseline: 1.3253x; 1.3253x over previous
#include <cuda_runtime.h>

// Fixed problem shapes: B=4, L=80000, N=512, F=257, STRIDE=256 -> T=311
#define NB  4
#define NL  80000
#define NN  512
#define NF  257
#define NT  311
#define BFT (NB * NF * NT)   // 319708

#define TWO_PI 6.2831853071795864769f

// ---------------------------------------------------------------------------
// Block = 256 threads (8 warps) per (frame t, batch b); grid (NT, NB).
// Thread (warp m, lane l) owns registers k=0,1 holding n = 32*(2m+k) + l.
//  H=256,128: fused radix-4 smem exchange (verified r10/11 formulas),
//    quartet slot q = m>>1 (warp-uniform), residual c = 2*(m&1)+k.
//  H=64: cross-warp smem butterfly (second buffer, second barrier),
//    twiddles identical to r11's H=64 stage.
//  H=32: register butterfly (k0,k1), twiddle -2*pi*l/64 (r11's).
//  H=16..1: verified shfl-xor butterflies on 2 regs.
//  Emit: f = 16*bitrev5(l) + 8k + bitrev3(m); one output per lane
//    (k=1 handed to odd neighbor); warp 0 lane 1 adds f=256.
// Output layout: floats [0,BFT) = spec; [BFT,2*BFT) = real(stft).
// ---------------------------------------------------------------------------
__global__ void __launch_bounds__(256, 6)
adstft_kernel(const float* __restrict__ x,
              const float* __restrict__ wlp,
              const float* __restrict__ stp,
              float* __restrict__ out) {
    __shared__ float2 s1[16][32];   // [kk][lane], input to radix-4
    __shared__ float2 s2[16][32];   // H=64 exchange

    const int t = blockIdx.x;
    const int b = blockIdx.y;
    const int m = threadIdx.x >> 5;
    const int l = threadIdx.x & 31;

    const float wl = fminf(fmaxf(wlp[0], 25.6f), 512.0f);   // WIN_MIN..WIN_MAX
    const float st = fminf(fmaxf(stp[0], 0.0f), 512.0f);    // STRIDE_MIN..MAX
    const float frame = st * (float)t;                       // == cumsum for integral st
    const float flo   = floorf(frame);
    const float frac  = frame - flo;
    const int   i0    = (int)flo;
    const float hi    = ceilf ((511.0f + wl) * 0.5f);
    const float lo    = floorf((511.0f - wl) * 0.5f);
    const float woff  = (wl - 511.0f) * 0.5f;

    // ---- Load + window ----
    {
        const float* xb = x + b * NL;
#pragma unroll
        for (int k = 0; k < 2; ++k) {
            const int n   = 32 * (2 * m + k) + l;
            const int idx = i0 + n;
            const float v = ((unsigned)idx < (unsigned)NL) ? xb[idx] : 0.0f;
            const float base = (float)n - frac;
            float tap = 0.0f;
            if (!(base >= hi || base <= lo))
                tap = (0.5f - 0.5f * __cosf(TWO_PI * (base + woff) / wl))
                      * 0.00390625f;                         // / N * 2
            s1[2 * m + k][l] = make_float2(v * tap, 0.0f);
        }
    }
    __syncthreads();

    // ---- Fused radix-4 cross-warp stages (H=256 then H=128) ----
    // Quartet {c, c+4, c+8, c+12}; this thread is slot q = m>>1 of quartet c.
    float zr[2], zi[2];
    {
        const int q = m >> 1;                         // warp-uniform
        float wlr, wli;                               // w(l) = e^{-2*pi*i*l/512}
        __sincosf(-TWO_PI * (float)l * (1.0f / 512.0f), &wli, &wlr);
        const float KC[4] = {1.0f, 0.92387953f,  0.70710678f,  0.38268343f};
        const float KS[4] = {0.0f, -0.38268343f, -0.70710678f, -0.92387953f};
#pragma unroll
        for (int k = 0; k < 2; ++k) {
            const int c = 2 * (m & 1) + k;            // kk mod 4
            // wA = w(l) * e^{-i*pi*c/8}
            const float wAr = wlr * KC[c] - wli * KS[c];
            const float wAi = wlr * KS[c] + wli * KC[c];

            const float2 c0 = s1[c     ][l];
            const float2 c1 = s1[c +  4][l];
            const float2 c2 = s1[c +  8][l];
            const float2 c3 = s1[c + 12][l];
            const float s0r = c0.x + c2.x, s0i = c0.y + c2.y;
            const float s1r = c1.x + c3.x, s1i = c1.y + c3.y;
            const float d0r = c0.x - c2.x, d0i = c0.y - c2.y;
            const float d1r = c1.x - c3.x, d1i = c1.y - c3.y;

            float rr, ri;
            if (q == 0) {                       // B0 = s0 + s1
                rr = s0r + s1r; ri = s0i + s1i;
            } else if (q == 1) {                // B1 = (s0 - s1) * wA^2
                const float wBr = wAr * wAr - wAi * wAi;
                const float wBi = 2.0f * wAr * wAi;
                const float er = s0r - s1r, ei = s0i - s1i;
                rr = er * wBr - ei * wBi;
                ri = er * wBi + ei * wBr;
            } else if (q == 2) {                // B2 = wA * (d0 - i*d1)
                const float er = d0r + d1i, ei = d0i - d1r;
                rr = er * wAr - ei * wAi;
                ri = er * wAi + ei * wAr;
            } else {                            // B3 = wA^3 * (d0 + i*d1)
                const float wBr = wAr * wAr - wAi * wAi;
                const float wBi = 2.0f * wAr * wAi;
                const float wCr = wAr * wBr - wAi * wBi;
                const float wCi = wAr * wBi + wAi * wBr;
                const float er = d0r - d1i, ei = d0i + d1r;
                rr = er * wCr - ei * wCi;
                ri = er * wCi + ei * wCr;
            }
            zr[k] = rr; zi[k] = ri;
        }
    }

    // ---- H=64: cross-warp butterfly via s2 (pairs kk, kk^2 <=> m, m^1) ----
    s2[2 * m    ][l] = make_float2(zr[0], zi[0]);
    s2[2 * m + 1][l] = make_float2(zr[1], zi[1]);
    __syncthreads();
    {
        // k=0 twiddle: e^{-i*pi*l/64}; k=1 twiddle = (-i) * that  (angle -pi/2)
        float t0i, t0r;
        __sincosf(-TWO_PI * (float)l * (1.0f / 128.0f), &t0i, &t0r);
        const float t1r = t0i;          // (-i)*(c+is) = s - ic
        const float t1i = -t0r;
        const bool top = ((m & 1) == 0);
#pragma unroll
        for (int k = 0; k < 2; ++k) {
            const float2 p = s2[(2 * m + k) ^ 2][l];
            if (top) {
                zr[k] += p.x;
                zi[k] += p.y;
            } else {
                const float dr = p.x - zr[k];
                const float di = p.y - zi[k];
                const float Tr = k ? t1r : t0r;
                const float Ti = k ? t1i : t0i;
                zr[k] = fmaf(dr, Tr, -di * Ti);
                zi[k] = fmaf(dr, Ti,  di * Tr);
            }
        }
    }

    // ---- H=32: register butterfly (k=0 top, k=1 bottom) ----
    {
        float sn, c;
        __sincosf(-TWO_PI * (float)l * (1.0f / 64.0f), &sn, &c);
        const float dr = zr[0] - zr[1];
        const float di = zi[0] - zi[1];
        zr[0] += zr[1];
        zi[0] += zi[1];
        zr[1] = fmaf(dr, c,  -di * sn);
        zi[1] = fmaf(dr, sn,  di * c);
    }

    // ---- Shfl stages H=16..1 on each register ----
#pragma unroll
    for (int h = 16; h >= 1; h >>= 1) {
        const int step = 16 / h;
        float twn, twc;
        __sincosf(-TWO_PI * (float)(step * (l & (h - 1))) * (1.0f / 32.0f),
                  &twn, &twc);
        const bool bot = (l & h) != 0;
#pragma unroll
        for (int k = 0; k < 2; ++k) {
            const float pr = __shfl_xor_sync(0xffffffffu, zr[k], h);
            const float pi = __shfl_xor_sync(0xffffffffu, zi[k], h);
            const float dr = pr - zr[k];
            const float di = pi - zi[k];
            const float tr = fmaf(dr, twc, -di * twn);
            const float ti = fmaf(dr, twn,  di * twc);
            zr[k] = bot ? tr : (zr[k] + pr);
            zi[k] = bot ? ti : (zi[k] + pi);
        }
    }

    // ---- Emit: f = 16*bitrev5(l) + 8k + bitrev3(m); one output per lane ----
    const int q5 = ((l & 1) << 4) | ((l & 2) << 2) | (l & 4)
                 | ((l & 8) >> 2) | ((l & 16) >> 4);          // bitrev5(l)
    const int brm3 = ((m & 1) << 2) | (m & 2) | ((m & 4) >> 2); // bitrev3(m)

    const float pr1 = __shfl_xor_sync(0xffffffffu, zr[1], 1);
    const float pi1 = __shfl_xor_sync(0xffffffffu, zi[1], 1);

    int f;
    float er, ei;
    if ((l & 1) == 0) {            // own k=0: f has bit3 = 0
        f  = (q5 << 4) | brm3;
        er = zr[0]; ei = zi[0];
    } else {                       // neighbor's k=1: f has bit3 = 1
        f  = (((q5 - 16) << 4) | brm3) | 8;
        er = pr1; ei = pi1;
    }

    {
        float sp, cp;
        __sincosf(TWO_PI * frac * (float)f * (1.0f / 512.0f), &sp, &cp);
        const float re = fmaf(er, cp, -ei * sp);
        const float im = fmaf(er, sp,  ei * cp);
        const int o = (b * NF + f) * NT + t;
        out[o]       = sqrtf(fmaf(re, re, im * im)) + 1.1920929e-7f;
        out[BFT + o] = re;
    }

    if (l == 1 && m == 0) {        // own (q5=16, kk=0) slot -> f = 256
        float sp, cp;
        __sincosf(TWO_PI * frac * 0.5f, &sp, &cp);
        const float re = fmaf(zr[0], cp, -zi[0] * sp);
        const float im = fmaf(zr[0], sp,  zi[0] * cp);
        const int o = (b * NF + 256) * NT + t;
        out[o]       = sqrtf(fmaf(re, re, im * im)) + 1.1920929e-7f;
        out[BFT + o] = re;
    }
}

// ---------------------------------------------------------------------------
extern "C" void kernel_launch(void* const* d_in, const int* in_sizes, int n_in,
                              void* d_out, int out_size) {
    // x is the unique large input; win_length is the middle input under both
    // insertion and alphabetical order; strides is the remaining small one.
    int ix = 0;
    for (int i = 1; i < n_in; ++i)
        if (in_sizes[i] > in_sizes[ix]) ix = i;
    const float* x  = (const float*)d_in[ix];
    const float* wl = (const float*)d_in[1];
    const float* st = (const float*)d_in[(ix == 0) ? 2 : 0];
    float* out = (float*)d_out;

    dim3 grid(NT, NB);
    adstft_kernel<<<grid, 256>>>(x, wl, st, out);
}

// round 14
// speedup vs baseline: 1.3887x; 1.0479x over previous
#include <cuda_runtime.h>

// Fixed problem shapes: B=4, L=80000, N=512, F=257, STRIDE=256 -> T=311
#define NB  4
#define NL  80000
#define NN  512
#define NF  257
#define NT  311
#define BFT (NB * NF * NT)   // 319708

#define TWO_PI 6.2831853071795864769f

__device__ __forceinline__ int bitrev4r(int v) {
    return ((v & 1) << 3) | ((v & 2) << 1) | ((v & 4) >> 1) | ((v & 8) >> 3);
}
__device__ __forceinline__ int bitrev5r(int v) {
    return ((v & 1) << 4) | ((v & 2) << 2) | (v & 4) | ((v & 8) >> 2) | ((v & 16) >> 4);
}

// ---------------------------------------------------------------------------
// Block = 256 threads (8 warps) per (frame t, batch-PAIR p); grid (NT, 2).
// Real-pair packing: z = g_{2p} + i*g_{2p+1}; ONE complex 512-FFT serves two
// batches. FFT pipeline identical to verified round 13:
//  H=256,128: fused radix-4 smem exchange; H=64: cross-warp smem butterfly;
//  H=32: register butterfly; H=16..1: shfl-xor butterflies.
// Then all 512 Z values are stashed to smem by position pos = 32*kk + l
// (bank=l, conflict-free; reuses the dead s1 buffer), and each lane unpacks
// its owned frequency f (r13 assignment) for BOTH batches:
//   F0 = (Z[f] + conj(Z[fb]))/2,  F1 = -i*(Z[f] - conj(Z[fb]))/2,
//   fb = (512-f) & 511,  pos(f) = 32*bitrev4(f&15) + bitrev5(f>>4).
// Output layout: floats [0,BFT) = spec; [BFT,2*BFT) = real(stft).
// ---------------------------------------------------------------------------
__global__ void __launch_bounds__(256, 6)
adstft_kernel(const float* __restrict__ x,
              const float* __restrict__ wlp,
              const float* __restrict__ stp,
              float* __restrict__ out) {
    __shared__ float2 s1[16][32];   // radix-4 input; later reused as Z stash
    __shared__ float2 s2[16][32];   // H=64 exchange

    const int t = blockIdx.x;
    const int p = blockIdx.y;       // batch pair: batches 2p, 2p+1
    const int m = threadIdx.x >> 5;
    const int l = threadIdx.x & 31;

    const float wl = fminf(fmaxf(wlp[0], 25.6f), 512.0f);   // WIN_MIN..WIN_MAX
    const float st = fminf(fmaxf(stp[0], 0.0f), 512.0f);    // STRIDE_MIN..MAX
    const float frame = st * (float)t;                       // == cumsum for integral st
    const float flo   = floorf(frame);
    const float frac  = frame - flo;
    const int   i0    = (int)flo;
    const float hi    = ceilf ((511.0f + wl) * 0.5f);
    const float lo    = floorf((511.0f - wl) * 0.5f);
    const float woff  = (wl - 511.0f) * 0.5f;

    // ---- Load + window: z = g_{2p} + i*g_{2p+1} ----
    {
        const float* xb0 = x + (2 * p) * NL;
        const float* xb1 = xb0 + NL;
#pragma unroll
        for (int k = 0; k < 2; ++k) {
            const int n   = 32 * (2 * m + k) + l;
            const int idx = i0 + n;
            const bool ok = ((unsigned)idx < (unsigned)NL);
            const float v0 = ok ? xb0[idx] : 0.0f;
            const float v1 = ok ? xb1[idx] : 0.0f;
            const float base = (float)n - frac;
            float tap = 0.0f;
            if (!(base >= hi || base <= lo))
                tap = (0.5f - 0.5f * __cosf(TWO_PI * (base + woff) / wl))
                      * 0.00390625f;                         // / N * 2
            s1[2 * m + k][l] = make_float2(v0 * tap, v1 * tap);
        }
    }
    __syncthreads();

    // ---- Fused radix-4 cross-warp stages (H=256 then H=128) ----
    float zr[2], zi[2];
    {
        const int q = m >> 1;                         // warp-uniform quartet slot
        float wlr, wli;                               // w(l) = e^{-2*pi*i*l/512}
        __sincosf(-TWO_PI * (float)l * (1.0f / 512.0f), &wli, &wlr);
        const float KC[4] = {1.0f, 0.92387953f,  0.70710678f,  0.38268343f};
        const float KS[4] = {0.0f, -0.38268343f, -0.70710678f, -0.92387953f};
#pragma unroll
        for (int k = 0; k < 2; ++k) {
            const int c = 2 * (m & 1) + k;            // kk mod 4
            const float wAr = wlr * KC[c] - wli * KS[c];
            const float wAi = wlr * KS[c] + wli * KC[c];

            const float2 c0 = s1[c     ][l];
            const float2 c1 = s1[c +  4][l];
            const float2 c2 = s1[c +  8][l];
            const float2 c3 = s1[c + 12][l];
            const float s0r = c0.x + c2.x, s0i = c0.y + c2.y;
            const float s1r = c1.x + c3.x, s1i = c1.y + c3.y;
            const float d0r = c0.x - c2.x, d0i = c0.y - c2.y;
            const float d1r = c1.x - c3.x, d1i = c1.y - c3.y;

            float rr, ri;
            if (q == 0) {                       // B0 = s0 + s1
                rr = s0r + s1r; ri = s0i + s1i;
            } else if (q == 1) {                // B1 = (s0 - s1) * wA^2
                const float wBr = wAr * wAr - wAi * wAi;
                const float wBi = 2.0f * wAr * wAi;
                const float er = s0r - s1r, ei = s0i - s1i;
                rr = er * wBr - ei * wBi;
                ri = er * wBi + ei * wBr;
            } else if (q == 2) {                // B2 = wA * (d0 - i*d1)
                const float er = d0r + d1i, ei = d0i - d1r;
                rr = er * wAr - ei * wAi;
                ri = er * wAi + ei * wAr;
            } else {                            // B3 = wA^3 * (d0 + i*d1)
                const float wBr = wAr * wAr - wAi * wAi;
                const float wBi = 2.0f * wAr * wAi;
                const float wCr = wAr * wBr - wAi * wBi;
                const float wCi = wAr * wBi + wAi * wBr;
                const float er = d0r - d1i, ei = d0i + d1r;
                rr = er * wCr - ei * wCi;
                ri = er * wCi + ei * wCr;
            }
            zr[k] = rr; zi[k] = ri;
        }
    }

    // ---- H=64: cross-warp butterfly via s2 (pairs kk, kk^2 <=> m, m^1) ----
    s2[2 * m    ][l] = make_float2(zr[0], zi[0]);
    s2[2 * m + 1][l] = make_float2(zr[1], zi[1]);
    __syncthreads();
    {
        float t0i, t0r;                 // k=0: e^{-2*pi*i*l/128}; k=1: -i * that
        __sincosf(-TWO_PI * (float)l * (1.0f / 128.0f), &t0i, &t0r);
        const float t1r = t0i;
        const float t1i = -t0r;
        const bool top = ((m & 1) == 0);
#pragma unroll
        for (int k = 0; k < 2; ++k) {
            const float2 pp = s2[(2 * m + k) ^ 2][l];
            if (top) {
                zr[k] += pp.x;
                zi[k] += pp.y;
            } else {
                const float dr = pp.x - zr[k];
                const float di = pp.y - zi[k];
                const float Tr = k ? t1r : t0r;
                const float Ti = k ? t1i : t0i;
                zr[k] = fmaf(dr, Tr, -di * Ti);
                zi[k] = fmaf(dr, Ti,  di * Tr);
            }
        }
    }

    // ---- H=32: register butterfly ----
    {
        float sn, c;
        __sincosf(-TWO_PI * (float)l * (1.0f / 64.0f), &sn, &c);
        const float dr = zr[0] - zr[1];
        const float di = zi[0] - zi[1];
        zr[0] += zr[1];
        zi[0] += zi[1];
        zr[1] = fmaf(dr, c,  -di * sn);
        zi[1] = fmaf(dr, sn,  di * c);
    }

    // ---- Shfl stages H=16..1 on each register ----
#pragma unroll
    for (int h = 16; h >= 1; h >>= 1) {
        const int step = 16 / h;
        float twn, twc;
        __sincosf(-TWO_PI * (float)(step * (l & (h - 1))) * (1.0f / 32.0f),
                  &twn, &twc);
        const bool bot = (l & h) != 0;
#pragma unroll
        for (int k = 0; k < 2; ++k) {
            const float pr = __shfl_xor_sync(0xffffffffu, zr[k], h);
            const float pi = __shfl_xor_sync(0xffffffffu, zi[k], h);
            const float dr = pr - zr[k];
            const float di = pi - zi[k];
            const float tr = fmaf(dr, twc, -di * twn);
            const float ti = fmaf(dr, twn,  di * twc);
            zr[k] = bot ? tr : (zr[k] + pr);
            zi[k] = bot ? ti : (zi[k] + pi);
        }
    }

    // ---- Stash all Z by position pos = 32*kk + l (s1 is dead; reuse) ----
    float* sZr = (float*)s1;            // [512]
    float* sZi = sZr + 512;             // [512]
    sZr[64 * m + l]      = zr[0];
    sZi[64 * m + l]      = zi[0];
    sZr[64 * m + 32 + l] = zr[1];
    sZi[64 * m + 32 + l] = zi[1];
    __syncthreads();

    // ---- Unpack + emit: each lane owns one f (r13 assignment); both batches ----
    const int q5   = bitrev5r(l);
    const int brm3 = ((m & 1) << 2) | (m & 2) | ((m & 4) >> 2);   // bitrev3(m)

    const int fown = ((l & 1) == 0) ? ((q5 << 4) | brm3)
                                    : ((((q5 - 16) << 4) | brm3) | 8);
    const int b0 = 2 * p;

    const int nEmit = (m == 0 && l == 1) ? 2 : 1;
    for (int e = 0; e < nEmit; ++e) {
        const int f = (e == 0) ? fown : 256;

        const int pos  = (bitrev4r(f & 15) << 5) | bitrev5r(f >> 4);
        const int fb   = (512 - f) & 511;
        const int posb = (bitrev4r(fb & 15) << 5) | bitrev5r(fb >> 4);

        const float Zr = sZr[pos],  Zi = sZi[pos];
        const float Yr = sZr[posb], Yi = sZi[posb];

        const float F0r = 0.5f * (Zr + Yr);
        const float F0i = 0.5f * (Zi - Yi);
        const float F1r = 0.5f * (Zi + Yi);
        const float F1i = 0.5f * (Yr - Zr);

        float sp, cp;                   // shift e^{+2*pi*i*frac*f/512}
        __sincosf(TWO_PI * frac * (float)f * (1.0f / 512.0f), &sp, &cp);

        const float re0 = fmaf(F0r, cp, -F0i * sp);
        const float im0 = fmaf(F0r, sp,  F0i * cp);
        const float re1 = fmaf(F1r, cp, -F1i * sp);
        const float im1 = fmaf(F1r, sp,  F1i * cp);

        const int o0 = (b0 * NF + f) * NT + t;
        const int o1 = o0 + NF * NT;
        out[o0]       = sqrtf(fmaf(re0, re0, im0 * im0)) + 1.1920929e-7f;
        out[BFT + o0] = re0;
        out[o1]       = sqrtf(fmaf(re1, re1, im1 * im1)) + 1.1920929e-7f;
        out[BFT + o1] = re1;
    }
}

// ---------------------------------------------------------------------------
extern "C" void kernel_launch(void* const* d_in, const int* in_sizes, int n_in,
                              void* d_out, int out_size) {
    // x is the unique large input; win_length is the middle input under both
    // insertion and alphabetical order; strides is the remaining small one.
    int ix = 0;
    for (int i = 1; i < n_in; ++i)
        if (in_sizes[i] > in_sizes[ix]) ix = i;
    const float* x  = (const float*)d_in[ix];
    const float* wl = (const float*)d_in[1];
    const float* st = (const float*)d_in[(ix == 0) ? 2 : 0];
    float* out = (float*)d_out;

    dim3 grid(NT, 2);
    adstft_kernel<<<grid, 256>>>(x, wl, st, out);
}